// round 2
// baseline (speedup 1.0000x reference)
#include <cuda_runtime.h>
#include <cstdint>

// Problem constants
#define F_NUM   104013      // feature dim (K of GEMM)
#define B_ROWS  1024        // batch (M of GEMM)
#define NCOLS   312         // field_num * K = 39*8  (valid v columns)
#define NPAD    320         // padded N: col 312 = w (linear), 313..319 = 0

// GEMM tiling
#define BM      128
#define BN      64
#define BK      16
#define NSTAGE  4
#define SPLITK  7
#define KCHUNK  14859       // F_NUM / SPLITK exactly (7*14859 = 104013)
#define NITERS  929         // ceil(14859/16)

// smem strides (floats), padded for bank conflicts + 16B alignment
#define SA      132         // A tile row stride (transposed As[BK][SA])
#define SB      68          // B tile row stride (Bs[BK][SB])
#define SMEM_BYTES ((NSTAGE*BK*SA + NSTAGE*BK*SB) * 4)   // 51200 B

// split-K partial results scratch: [SPLITK][B_ROWS][NPAD]
__device__ float g_part[SPLITK * B_ROWS * NPAD];

__device__ __forceinline__ unsigned smem_u32(const void* p) {
    return (unsigned)__cvta_generic_to_shared(p);
}
__device__ __forceinline__ void cpa4(unsigned dst, const void* src, int sbytes) {
    asm volatile("cp.async.ca.shared.global [%0], [%1], 4, %2;\n"
                 :: "r"(dst), "l"(src), "r"(sbytes));
}
__device__ __forceinline__ void cpa16(unsigned dst, const void* src, int sbytes) {
    asm volatile("cp.async.cg.shared.global [%0], [%1], 16, %2;\n"
                 :: "r"(dst), "l"(src), "r"(sbytes));
}

// D[bz][m][n] partial = X[m, krange(bz)] @ Vcat[krange(bz), n]
// Vcat col n<312 = v[:, n], col 312 = w, col>312 = 0
__global__ void __launch_bounds__(256)
fm_gemm(const float* __restrict__ X, const float* __restrict__ W,
        const float* __restrict__ V) {
    extern __shared__ float smem[];
    float* sA = smem;                      // [NSTAGE][BK][SA]
    float* sB = smem + NSTAGE * BK * SA;   // [NSTAGE][BK][SB]

    const int t  = threadIdx.x;
    const int bx = blockIdx.x;   // n tile: 0..4
    const int by = blockIdx.y;   // m tile: 0..7
    const int bz = blockIdx.z;   // split:  0..6

    const int m0   = by * BM;
    const int n0   = bx * BN;
    const int k0   = bz * KCHUNK;
    const int kend = k0 + KCHUNK;

    // loader mapping
    const int a_kk = t & 15;     // k within tile (lanes k-major -> coalesced LDG)
    const int a_rb = t >> 4;     // row base 0..15 (8 rows per thread, stride 16)
    const int b_kk = t >> 4;     // 0..15
    const int b_cg = t & 15;     // col group (4 floats)

    // compute mapping: thread tile 4 rows x 8 cols
    const int tx = t & 7;        // col group of 8 -> cols tx*8 .. tx*8+7
    const int ty = t >> 3;       // 0..31       -> rows ty*4 .. ty*4+3

    unsigned long long acc[4][4];   // [m][j]: f32x2 pair for cols (2j, 2j+1)
#pragma unroll
    for (int m = 0; m < 4; ++m)
#pragma unroll
        for (int j = 0; j < 4; ++j) acc[m][j] = 0ull;

    auto load_stage = [&](int st, int it) {
        const int kt = k0 + it * BK;
        // ---- A tile: 128 rows x 16 k (scalar cp.async, odd row stride) ----
        unsigned sa_base = smem_u32(sA + st * BK * SA);
        const int ka   = kt + a_kk;
        const int asz  = (ka < kend) ? 4 : 0;
        const float* arow0 = X + m0 * F_NUM + ka;
#pragma unroll
        for (int p = 0; p < 8; ++p) {
            const int row = a_rb + p * 16;
            const float* s = asz ? (arow0 + row * F_NUM) : X;
            cpa4(sa_base + (unsigned)((a_kk * SA + row) * 4), s, asz);
        }
        // ---- B tile: 16 k x 64 cols (vector cp.async on v, col312=w, pad=0) ----
        unsigned sb_base = smem_u32(sB + st * BK * SB);
        const int ks  = kt + b_kk;
        const int bsz = (ks < kend) ? 16 : 0;
        const int col = n0 + b_cg * 4;
        const unsigned sdst = sb_base + (unsigned)((b_kk * SB + b_cg * 4) * 4);
        if (col + 3 < NCOLS) {
            const float* s = bsz ? (V + ks * NCOLS + col) : V;
            cpa16(sdst, s, bsz);
        } else {
            // only bx==4, b_cg>=14: cols 312..319
#pragma unroll
            for (int cc = 0; cc < 4; ++cc) {
                const int c = col + cc;
                int sz; const float* s;
                if (c == NCOLS) { sz = bsz ? 4 : 0; s = sz ? (W + ks) : W; }
                else            { sz = 0;           s = W; }
                cpa4(sdst + (unsigned)(cc * 4), s, sz);
            }
        }
    };

    // prologue: NSTAGE-1 stages in flight
#pragma unroll
    for (int s = 0; s < NSTAGE - 1; ++s) {
        load_stage(s, s);
        asm volatile("cp.async.commit_group;\n");
    }

    for (int it = 0; it < NITERS; ++it) {
        asm volatile("cp.async.wait_group %0;\n" :: "n"(NSTAGE - 2));
        __syncthreads();   // stage `it` visible to all; prev compute stage free
        {
            const int nt = it + NSTAGE - 1;
            if (nt < NITERS) load_stage(nt & (NSTAGE - 1), nt);
            asm volatile("cp.async.commit_group;\n");
        }
        const int st = it & (NSTAGE - 1);
        const float* cA = sA + st * BK * SA + ty * 4;
        const unsigned bbase = smem_u32(sB + st * BK * SB) + (unsigned)(tx * 32);
#pragma unroll
        for (int k = 0; k < BK; ++k) {
            const float4 av = *reinterpret_cast<const float4*>(cA + k * SA);
            unsigned long long b[4];
#pragma unroll
            for (int j = 0; j < 4; ++j)
                asm volatile("ld.shared.b64 %0, [%1];"
                             : "=l"(b[j]) : "r"(bbase + (unsigned)(k * SB * 4 + j * 8)));
            const uint32_t au[4] = {__float_as_uint(av.x), __float_as_uint(av.y),
                                    __float_as_uint(av.z), __float_as_uint(av.w)};
#pragma unroll
            for (int m = 0; m < 4; ++m) {
                unsigned long long ad;
                asm("mov.b64 %0, {%1, %2};" : "=l"(ad) : "r"(au[m]), "r"(au[m]));
#pragma unroll
                for (int j = 0; j < 4; ++j)
                    asm("fma.rn.f32x2 %0, %1, %2, %0;"
                        : "+l"(acc[m][j]) : "l"(ad), "l"(b[j]));
            }
        }
    }
    asm volatile("cp.async.wait_group 0;\n");

    // store partial tile
    float* outp = g_part + (bz * B_ROWS + m0) * NPAD + n0;
#pragma unroll
    for (int m = 0; m < 4; ++m) {
        const int r = ty * 4 + m;
#pragma unroll
        for (int j = 0; j < 4; ++j) {
            uint32_t lo, hi;
            asm("mov.b64 {%0, %1}, %2;" : "=r"(lo), "=r"(hi) : "l"(acc[m][j]));
            *reinterpret_cast<float2*>(outp + r * NPAD + tx * 8 + j * 2) =
                make_float2(__uint_as_float(lo), __uint_as_float(hi));
        }
    }
}

// out[b] = w0 + linear + 0.5*(||sum_i f_i||^2 - sum_i ||f_i||^2)
__global__ void __launch_bounds__(128)
fm_epilogue(const float* __restrict__ w0, float* __restrict__ out) {
    const int b = blockIdx.x;
    const int t = threadIdx.x;
    __shared__ float row[NPAD];
    __shared__ float red[128];
    __shared__ float skq[8];

    for (int c = t; c < NPAD; c += 128) {
        float v = 0.f;
#pragma unroll
        for (int s = 0; s < SPLITK; ++s)
            v += g_part[(s * B_ROWS + b) * NPAD + c];
        row[c] = v;
    }
    __syncthreads();

    float sq = 0.f;
    for (int c = t; c < NCOLS; c += 128) sq += row[c] * row[c];
    red[t] = sq;
    __syncthreads();
#pragma unroll
    for (int off = 64; off > 0; off >>= 1) {
        if (t < off) red[t] += red[t + off];
        __syncthreads();
    }
    if (t < 8) {
        float s = 0.f;
#pragma unroll
        for (int i = 0; i < 39; ++i) s += row[i * 8 + t];
        skq[t] = s * s;
    }
    __syncthreads();
    if (t == 0) {
        const float s2 = skq[0] + skq[1] + skq[2] + skq[3]
                       + skq[4] + skq[5] + skq[6] + skq[7];
        out[b] = w0[0] + row[NCOLS] + 0.5f * (s2 - red[0]);
    }
}

extern "C" void kernel_launch(void* const* d_in, const int* in_sizes, int n_in,
                              void* d_out, int out_size) {
    const float* X  = (const float*)d_in[0];   // inputs [1024, 104013]
    const float* w0 = (const float*)d_in[1];   // [1]
    const float* W  = (const float*)d_in[2];   // [104013, 1]
    const float* V  = (const float*)d_in[3];   // [104013, 39, 8] == [104013, 312]
    float* out = (float*)d_out;                // [1024, 1]

    cudaFuncSetAttribute(fm_gemm, cudaFuncAttributeMaxDynamicSharedMemorySize,
                         SMEM_BYTES);
    dim3 grid(NPAD / BN, B_ROWS / BM, SPLITK);   // 5 x 8 x 7 = 280 CTAs
    fm_gemm<<<grid, 256, SMEM_BYTES>>>(X, W, V);
    fm_epilogue<<<B_ROWS, 128>>>(w0, out);
}

// round 6
// speedup vs baseline: 2.5088x; 2.5088x over previous
#include <cuda_runtime.h>
#include <cuda_bf16.h>
#include <cstdint>

// ---------------- problem constants ----------------
#define F_NUM   104013
#define KP      104064              // padded K: 3252 * 32
#define B_ROWS  1024
#define NCOLS   312
#define NPAD    320                 // col 312 = w, 313..319 = 0

// ---------------- GEMM tiling ----------------
#define BM        64
#define BN        320               // full N per CTA
#define BK        32
#define KT        3252              // KP / 32
#define SPLITK    9
#define TILES_PER 362               // ceil(3252/9)
#define NST       3

// stage smem layout (bytes); 80B row pitch (64B data + 16 pad)
#define A_PITCH   80
#define A_TILE    (64 * 80)         // 5120
#define B_TILE    (320 * 80)        // 25600
#define STG       (2 * A_TILE + 2 * B_TILE)   // 61440
#define SMEM_TOT  (NST * STG)       // 184320

// ---------------- device scratch ----------------
__device__ unsigned short g_xhi [(size_t)B_ROWS * KP];
__device__ unsigned short g_xlo [(size_t)B_ROWS * KP];
__device__ unsigned short g_vthi[(size_t)NPAD * KP];
__device__ unsigned short g_vtlo[(size_t)NPAD * KP];
__device__ float          g_part[(size_t)SPLITK * B_ROWS * NPAD];

// ---------------- helpers ----------------
__device__ __forceinline__ unsigned smem_u32(const void* p) {
    return (unsigned)__cvta_generic_to_shared(p);
}
__device__ __forceinline__ void cpa16(unsigned dst, const void* src) {
    asm volatile("cp.async.cg.shared.global [%0], [%1], 16;\n" :: "r"(dst), "l"(src));
}
__device__ __forceinline__ void ldsm4(uint32_t* r, unsigned a) {
    asm volatile("ldmatrix.sync.aligned.m8n8.x4.shared.b16 {%0,%1,%2,%3}, [%4];"
                 : "=r"(r[0]), "=r"(r[1]), "=r"(r[2]), "=r"(r[3]) : "r"(a));
}
__device__ __forceinline__ void mma16816(float* c, const uint32_t* a, const uint32_t* b) {
    asm volatile("mma.sync.aligned.m16n8k16.row.col.f32.bf16.bf16.f32 "
                 "{%0,%1,%2,%3}, {%4,%5,%6,%7}, {%8,%9}, {%0,%1,%2,%3};"
                 : "+f"(c[0]), "+f"(c[1]), "+f"(c[2]), "+f"(c[3])
                 : "r"(a[0]), "r"(a[1]), "r"(a[2]), "r"(a[3]), "r"(b[0]), "r"(b[1]));
}
__device__ __forceinline__ unsigned short bf2u(__nv_bfloat16 h) {
    return *reinterpret_cast<unsigned short*>(&h);
}

// ---------------- convert X -> bf16 hi/lo, padded ----------------
__global__ void __launch_bounds__(256)
cvt_x(const float* __restrict__ X) {
    const int m  = blockIdx.y;
    const int kp = blockIdx.x * 256 + threadIdx.x;
    if (kp >= KP) return;
    float v = (kp < F_NUM) ? X[(size_t)m * F_NUM + kp] : 0.f;
    __nv_bfloat16 h = __float2bfloat16(v);
    __nv_bfloat16 l = __float2bfloat16(v - __bfloat162float(h));
    size_t o = (size_t)m * KP + kp;
    g_xhi[o] = bf2u(h);
    g_xlo[o] = bf2u(l);
}

// ---------------- convert+transpose Vcat -> [320][KP] bf16 hi/lo ----------------
__global__ void __launch_bounds__(256)
cvt_v(const float* __restrict__ V, const float* __restrict__ W) {
    __shared__ unsigned short sh[32][130];
    __shared__ unsigned short sl[32][130];
    const int k0 = blockIdx.x * 128;
    const int n0 = blockIdx.y * 32;
    const int t  = threadIdx.x;
    const int j  = t & 31;      // n within tile
    const int i0 = t >> 5;      // k row base (stride 8)
#pragma unroll
    for (int p = 0; p < 16; ++p) {
        const int i = i0 + p * 8;          // k row 0..127
        const int k = k0 + i, n = n0 + j;
        float v = 0.f;
        if (k < F_NUM) {
            if (n < NCOLS)       v = V[(size_t)k * NCOLS + n];
            else if (n == NCOLS) v = W[k];
        }
        __nv_bfloat16 h = __float2bfloat16(v);
        sh[j][i] = bf2u(h);
        sl[j][i] = bf2u(__float2bfloat16(v - __bfloat162float(h)));
    }
    __syncthreads();
    const int r  = t >> 3;      // n row 0..31
    const int c8 = t & 7;       // 16-elem chunk
    const size_t ob = (size_t)(n0 + r) * KP + k0 + c8 * 16;
    uint32_t ph[8], pl[8];
#pragma unroll
    for (int q = 0; q < 8; ++q) {
        ph[q] = (uint32_t)sh[r][c8*16 + 2*q] | ((uint32_t)sh[r][c8*16 + 2*q + 1] << 16);
        pl[q] = (uint32_t)sl[r][c8*16 + 2*q] | ((uint32_t)sl[r][c8*16 + 2*q + 1] << 16);
    }
    uint4* dh = reinterpret_cast<uint4*>(g_vthi + ob);
    uint4* dl = reinterpret_cast<uint4*>(g_vtlo + ob);
    dh[0] = make_uint4(ph[0], ph[1], ph[2], ph[3]);
    dh[1] = make_uint4(ph[4], ph[5], ph[6], ph[7]);
    dl[0] = make_uint4(pl[0], pl[1], pl[2], pl[3]);
    dl[1] = make_uint4(pl[4], pl[5], pl[6], pl[7]);
}

// ---------------- HMMA bf16-split GEMM ----------------
__global__ void __launch_bounds__(256, 1)
fm_gemm() {
    extern __shared__ char smem[];
    const unsigned sbase = smem_u32(smem);
    const int t    = threadIdx.x;
    const int lane = t & 31;
    const int wid  = t >> 5;
    const int wm   = wid >> 2;     // 0..1  (32-row slice)
    const int wn   = wid & 3;      // 0..3  (80-col slice)
    const int m0   = blockIdx.x * BM;
    const int bz   = blockIdx.z;

    const int tile0 = bz * TILES_PER;
    const int T = min(TILES_PER, KT - tile0);

    float acc[2][10][4];
#pragma unroll
    for (int a = 0; a < 2; ++a)
#pragma unroll
        for (int b = 0; b < 10; ++b)
#pragma unroll
            for (int c = 0; c < 4; ++c) acc[a][b][c] = 0.f;

    // ---- loader per-thread constants ----
    const int ar  = t >> 2, akc = t & 3;                 // A: 256 chunks of 16B
    const size_t a_src = (size_t)(m0 + ar) * KP + akc * 8;
    const unsigned a_dst = (unsigned)(ar * A_PITCH + akc * 16);

    auto load_stage = [&](int slot, int jt) {
        const unsigned tb = sbase + (unsigned)slot * STG;
        const size_t kel = (size_t)jt * BK;
        cpa16(tb + a_dst,          g_xhi + a_src + kel);
        cpa16(tb + A_TILE + a_dst, g_xlo + a_src + kel);
#pragma unroll
        for (int i = 0; i < 5; ++i) {
            const int c = t + i * 256;
            const int row = c >> 2, kc = c & 3;
            const unsigned d = (unsigned)(row * A_PITCH + kc * 16);
            const size_t s = (size_t)row * KP + kel + kc * 8;
            cpa16(tb + 2u * A_TILE + d,          g_vthi + s);
            cpa16(tb + 2u * A_TILE + B_TILE + d, g_vtlo + s);
        }
    };

    // ---- ldmatrix per-lane offsets ----
    const unsigned a_loff = (unsigned)((wm * 32 + (lane & 15)) * A_PITCH + (lane >> 4) * 16);
    const unsigned b_loff = (unsigned)((wn * 80 + (lane & 7) + ((lane & 16) >> 1)) * A_PITCH
                                       + ((lane & 8) << 1));
    const unsigned bh_base = 2u * A_TILE;
    const unsigned bl_base = 2u * A_TILE + B_TILE;

    load_stage(0, tile0 + 0);
    asm volatile("cp.async.commit_group;\n");
    load_stage(1, tile0 + 1);
    asm volatile("cp.async.commit_group;\n");

    for (int it = 0; it < T; ++it) {
        asm volatile("cp.async.wait_group 1;\n");
        __syncthreads();

        const int j = it + 2;
        if (j < T) load_stage((it + 2) % NST, tile0 + j);
        asm volatile("cp.async.commit_group;\n");

        const unsigned tb = sbase + (unsigned)(it % NST) * STG;
#pragma unroll
        for (int kk = 0; kk < 2; ++kk) {
            uint32_t ah[8], al[8], bb[20];
            ldsm4(ah,     tb + a_loff + kk * 32);
            ldsm4(ah + 4, tb + a_loff + 16 * A_PITCH + kk * 32);
            ldsm4(al,     tb + A_TILE + a_loff + kk * 32);
            ldsm4(al + 4, tb + A_TILE + a_loff + 16 * A_PITCH + kk * 32);
#pragma unroll
            for (int p = 0; p < 5; ++p)
                ldsm4(bb + p * 4, tb + bh_base + b_loff + p * 16 * A_PITCH + kk * 32);
            // pass 1: hi*hi ; pass 2: lo*hi
#pragma unroll
            for (int mt = 0; mt < 2; ++mt)
#pragma unroll
                for (int nt = 0; nt < 10; ++nt) {
                    mma16816(acc[mt][nt], (mt ? ah + 4 : ah), bb + nt * 2);
                    mma16816(acc[mt][nt], (mt ? al + 4 : al), bb + nt * 2);
                }
            // pass 3: hi*lo
#pragma unroll
            for (int p = 0; p < 5; ++p)
                ldsm4(bb + p * 4, tb + bl_base + b_loff + p * 16 * A_PITCH + kk * 32);
#pragma unroll
            for (int mt = 0; mt < 2; ++mt)
#pragma unroll
                for (int nt = 0; nt < 10; ++nt)
                    mma16816(acc[mt][nt], (mt ? ah + 4 : ah), bb + nt * 2);
        }
    }
    asm volatile("cp.async.wait_group 0;\n");

    // ---- store partials ----
    const int r0 = m0 + wm * 32 + (lane >> 2);
    const int c0 = wn * 80 + 2 * (lane & 3);
    float* base = g_part + (size_t)bz * B_ROWS * NPAD;
#pragma unroll
    for (int mt = 0; mt < 2; ++mt)
#pragma unroll
        for (int nt = 0; nt < 10; ++nt) {
            const int r = r0 + mt * 16, c = c0 + nt * 8;
            *reinterpret_cast<float2*>(base + (size_t)r * NPAD + c) =
                make_float2(acc[mt][nt][0], acc[mt][nt][1]);
            *reinterpret_cast<float2*>(base + (size_t)(r + 8) * NPAD + c) =
                make_float2(acc[mt][nt][2], acc[mt][nt][3]);
        }
}

// ---------------- epilogue: FM identity ----------------
__global__ void __launch_bounds__(128)
fm_epilogue(const float* __restrict__ w0, float* __restrict__ out) {
    const int b = blockIdx.x;
    const int t = threadIdx.x;
    __shared__ float row[NPAD];
    __shared__ float red[128];
    __shared__ float skq[8];

    for (int c = t; c < NPAD; c += 128) {
        float v = 0.f;
#pragma unroll
        for (int s = 0; s < SPLITK; ++s)
            v += g_part[((size_t)(s * B_ROWS + b)) * NPAD + c];
        row[c] = v;
    }
    __syncthreads();

    float sq = 0.f;
    for (int c = t; c < NCOLS; c += 128) sq += row[c] * row[c];
    red[t] = sq;
    __syncthreads();
#pragma unroll
    for (int off = 64; off > 0; off >>= 1) {
        if (t < off) red[t] += red[t + off];
        __syncthreads();
    }
    if (t < 8) {
        float s = 0.f;
#pragma unroll
        for (int i = 0; i < 39; ++i) s += row[i * 8 + t];
        skq[t] = s * s;
    }
    __syncthreads();
    if (t == 0) {
        const float s2 = skq[0] + skq[1] + skq[2] + skq[3]
                       + skq[4] + skq[5] + skq[6] + skq[7];
        out[b] = w0[0] + row[NCOLS] + 0.5f * (s2 - red[0]);
    }
}

extern "C" void kernel_launch(void* const* d_in, const int* in_sizes, int n_in,
                              void* d_out, int out_size) {
    const float* X  = (const float*)d_in[0];   // [1024, 104013]
    const float* w0 = (const float*)d_in[1];   // [1]
    const float* W  = (const float*)d_in[2];   // [104013, 1]
    const float* V  = (const float*)d_in[3];   // [104013, 312]
    float* out = (float*)d_out;                // [1024, 1]

    cvt_x<<<dim3((KP + 255) / 256, B_ROWS), 256>>>(X);
    cvt_v<<<dim3(KP / 128, NPAD / 32), 256>>>(V, W);

    cudaFuncSetAttribute(fm_gemm, cudaFuncAttributeMaxDynamicSharedMemorySize,
                         SMEM_TOT);
    fm_gemm<<<dim3(B_ROWS / BM, 1, SPLITK), 256, SMEM_TOT>>>();
    fm_epilogue<<<B_ROWS, 128>>>(w0, out);
}